// round 3
// baseline (speedup 1.0000x reference)
#include <cuda_runtime.h>
#include <cuda_bf16.h>
#include <math.h>

// Problem constants
#define B_  2
#define S_  2048
#define E_  2048
#define H_  16
#define KV_ 4
#define G_  (H_ / KV_)   // 4
#define D_  128
#define NTOK (B_ * S_)   // 4096

// Scratch (device globals: allocation-free rule)
__device__ float g_q[NTOK * (H_ * D_)];   // [4096, 2048]
__device__ float g_k[NTOK * (KV_ * D_)];  // [4096, 512]
__device__ float g_v[NTOK * (KV_ * D_)];  // [4096, 512]
__device__ float g_o[NTOK * (H_ * D_)];   // [4096, 2048]
__device__ float g_cos[S_ * 64];          // rope tables
__device__ float g_sin[S_ * 64];

// ---------------------------------------------------------------------------
// NAIVE GEMM: C[M,N] = A[M,K] @ B[K,N], row-major. One output per thread.
// Deliberately simple — bisect stage, structurally cannot have tiling bugs.
// ---------------------------------------------------------------------------
__global__ void __launch_bounds__(256)
ngemm_kernel(const float* __restrict__ A, const float* __restrict__ Bm,
             float* __restrict__ C, int M, int N, int K) {
    int n = blockIdx.x * 32 + (threadIdx.x & 31);
    int m = blockIdx.y * 8 + (threadIdx.x >> 5);
    if (m >= M || n >= N) return;
    float acc = 0.f;
    const float* a = A + (size_t)m * K;
    for (int k = 0; k < K; k++)
        acc = fmaf(a[k], Bm[(size_t)k * N + n], acc);
    C[(size_t)m * N + n] = acc;
}

// ---------------------------------------------------------------------------
// RoPE tables (double precision build): cos/sin[s][i] for angle s*10000^(-i/64)
// ---------------------------------------------------------------------------
__global__ void build_tables_kernel() {
    int idx = blockIdx.x * blockDim.x + threadIdx.x;
    if (idx >= S_ * 64) return;
    int i = idx & 63;
    int s = idx >> 6;
    double inv = pow(10000.0, -(double)i / 64.0);
    double ang = (double)s * inv;
    g_cos[idx] = (float)cos(ang);
    g_sin[idx] = (float)sin(ang);
}

// Apply rope in place. p: [NTOK, nheads*128].
// out[d]    = x[d]*cos - x[d+64]*sin   (d < 64)
// out[d+64] = x[d+64]*cos + x[d]*sin
__global__ void apply_rope_kernel(float* __restrict__ p, int nheads, int total) {
    int idx = blockIdx.x * blockDim.x + threadIdx.x;
    if (idx >= total) return;
    int i = idx & 63;
    int h = (idx >> 6) % nheads;
    int tok = idx / (nheads * 64);
    int s = tok & (S_ - 1);

    float c  = g_cos[s * 64 + i];
    float sn = g_sin[s * 64 + i];

    size_t base = (size_t)tok * (nheads * 128) + h * 128;
    float x1 = p[base + i];
    float x2 = p[base + 64 + i];
    p[base + i]      = x1 * c - x2 * sn;
    p[base + 64 + i] = x2 * c + x1 * sn;
}

// ---------------------------------------------------------------------------
// Flash attention (causal, online softmax), fp32, smem-staged probabilities.
// grid: (S/64, H, B), block 256 (8 warps). Warp w owns rows w*8..w*8+7.
// Lane owns output dims [lane*4, lane*4+4).
// ---------------------------------------------------------------------------
#define BQ 64
#define BKV 32
#define KS_STRIDE 132
#define SP_STRIDE 33

__global__ void __launch_bounds__(256)
attn_kernel(const float* __restrict__ q, const float* __restrict__ k,
            const float* __restrict__ v, float* __restrict__ o) {
    extern __shared__ float sm[];
    float* Qs  = sm;                         // [64][128]
    float* Ks  = Qs + BQ * 128;              // [32][132]
    float* Vs  = Ks + BKV * KS_STRIDE;       // [32][128]
    float* Sp  = Vs + BKV * 128;             // [64][33]
    float* m_s = Sp + BQ * SP_STRIDE;        // [64]
    float* l_s = m_s + BQ;                   // [64]
    float* c_s = l_s + BQ;                   // [64]

    const int qt = blockIdx.x, h = blockIdx.y, b = blockIdx.z;
    const int kvh = h >> 2;
    const int t = threadIdx.x, warp = t >> 5, lane = t & 31;
    const int q0 = qt * BQ;
    const int row0 = warp * 8;
    const float scale = 0.08838834764831845f;

    const float* qb = q + (size_t)(b * S_ + q0) * (H_ * D_) + h * D_;
    for (int i = t; i < BQ * 32; i += 256) {
        int r = i >> 5, c = (i & 31) << 2;
        *(float4*)(Qs + r * 128 + c) = *(const float4*)(qb + (size_t)r * (H_ * D_) + c);
    }
    if (t < BQ) { m_s[t] = -INFINITY; l_s[t] = 0.f; }

    float acc[8][4];
#pragma unroll
    for (int r = 0; r < 8; r++)
#pragma unroll
        for (int u = 0; u < 4; u++) acc[r][u] = 0.f;
    __syncthreads();

    for (int ks0 = 0; ks0 < q0 + BQ; ks0 += BKV) {
        const float* kb = k + (size_t)(b * S_ + ks0) * (KV_ * D_) + kvh * D_;
        const float* vb = v + (size_t)(b * S_ + ks0) * (KV_ * D_) + kvh * D_;
        for (int i = t; i < BKV * 32; i += 256) {
            int r = i >> 5, c = (i & 31) << 2;
            *(float4*)(Ks + r * KS_STRIDE + c) = *(const float4*)(kb + (size_t)r * (KV_ * D_) + c);
            *(float4*)(Vs + r * 128 + c)       = *(const float4*)(vb + (size_t)r * (KV_ * D_) + c);
        }
        __syncthreads();

        const int kpos = ks0 + lane;
#pragma unroll
        for (int r = 0; r < 8; r++) {
            float s = 0.f;
#pragma unroll
            for (int d4 = 0; d4 < 32; d4++) {
                float4 kd = *(const float4*)(Ks + lane * KS_STRIDE + d4 * 4);
                float4 qd = *(const float4*)(Qs + (row0 + r) * 128 + d4 * 4);
                s = fmaf(qd.x, kd.x, s);
                s = fmaf(qd.y, kd.y, s);
                s = fmaf(qd.z, kd.z, s);
                s = fmaf(qd.w, kd.w, s);
            }
            int qpos = q0 + row0 + r;
            Sp[(row0 + r) * SP_STRIDE + lane] = (kpos <= qpos) ? s * scale : -INFINITY;
        }
        __syncthreads();

        if (t < BQ) {
            float* sp = Sp + t * SP_STRIDE;
            float mold = m_s[t];
            float mloc = -INFINITY;
#pragma unroll
            for (int j = 0; j < BKV; j++) mloc = fmaxf(mloc, sp[j]);
            float mn = fmaxf(mold, mloc);
            float corr = expf(mold - mn);
            float sum = 0.f;
#pragma unroll
            for (int j = 0; j < BKV; j++) {
                float pj = expf(sp[j] - mn);
                sp[j] = pj;
                sum += pj;
            }
            l_s[t] = l_s[t] * corr + sum;
            m_s[t] = mn;
            c_s[t] = corr;
        }
        __syncthreads();

#pragma unroll
        for (int r = 0; r < 8; r++) {
            float corr = c_s[row0 + r];
#pragma unroll
            for (int u = 0; u < 4; u++) acc[r][u] *= corr;
        }
#pragma unroll 4
        for (int j = 0; j < BKV; j++) {
            float4 vv = *(const float4*)(Vs + j * 128 + lane * 4);
#pragma unroll
            for (int r = 0; r < 8; r++) {
                float pb = Sp[(row0 + r) * SP_STRIDE + j];
                acc[r][0] = fmaf(pb, vv.x, acc[r][0]);
                acc[r][1] = fmaf(pb, vv.y, acc[r][1]);
                acc[r][2] = fmaf(pb, vv.z, acc[r][2]);
                acc[r][3] = fmaf(pb, vv.w, acc[r][3]);
            }
        }
        __syncthreads();
    }

#pragma unroll
    for (int r = 0; r < 8; r++) {
        float inv = 1.f / l_s[row0 + r];
        float* ob = o + (size_t)(b * S_ + q0 + row0 + r) * (H_ * D_) + h * D_;
        float4 ov = make_float4(acc[r][0] * inv, acc[r][1] * inv,
                                acc[r][2] * inv, acc[r][3] * inv);
        *(float4*)(ob + lane * 4) = ov;
    }
}

// ---------------------------------------------------------------------------
// Launch
// ---------------------------------------------------------------------------
extern "C" void kernel_launch(void* const* d_in, const int* in_sizes, int n_in,
                              void* d_out, int out_size) {
    // Input mapping with runtime order check via element counts.
    // Expected (dict order):    x=8388608, Wq=4194304, Wk=1048576, Wv=1048576, Wo=4194304
    // Alphabetical fallback:    Wk, Wo, Wq, Wv, x
    const float *x, *Wq, *Wk, *Wv, *Wo;
    if (in_sizes[0] == NTOK * E_) {
        x  = (const float*)d_in[0];
        Wq = (const float*)d_in[1];
        Wk = (const float*)d_in[2];
        Wv = (const float*)d_in[3];
        Wo = (const float*)d_in[4];
    } else {
        // alphabetical: Wk, Wo, Wq, Wv, x
        Wk = (const float*)d_in[0];
        Wo = (const float*)d_in[1];
        Wq = (const float*)d_in[2];
        Wv = (const float*)d_in[3];
        x  = (const float*)d_in[4];
    }
    float* out = (float*)d_out;

    float *q, *k, *v, *o;
    cudaGetSymbolAddress((void**)&q, g_q);
    cudaGetSymbolAddress((void**)&k, g_k);
    cudaGetSymbolAddress((void**)&v, g_v);
    cudaGetSymbolAddress((void**)&o, g_o);

    const int attn_smem =
        (BQ * 128 + BKV * KS_STRIDE + BKV * 128 + BQ * SP_STRIDE + 3 * BQ) * (int)sizeof(float);
    cudaFuncSetAttribute(attn_kernel, cudaFuncAttributeMaxDynamicSharedMemorySize, attn_smem);

    // 0) rope tables
    build_tables_kernel<<<(S_ * 64 + 255) / 256, 256>>>();

    // 1) projections (naive GEMM — bisect stage)
    {
        dim3 gq((H_ * D_ + 31) / 32, (NTOK + 7) / 8);
        ngemm_kernel<<<gq, 256>>>(x, Wq, q, NTOK, H_ * D_, E_);
        dim3 gk((KV_ * D_ + 31) / 32, (NTOK + 7) / 8);
        ngemm_kernel<<<gk, 256>>>(x, Wk, k, NTOK, KV_ * D_, E_);
        ngemm_kernel<<<gk, 256>>>(x, Wv, v, NTOK, KV_ * D_, E_);
    }

    // 2) RoPE (in place, table-based)
    {
        int totq = NTOK * H_ * 64;
        apply_rope_kernel<<<(totq + 255) / 256, 256>>>(q, H_, totq);
        int totk = NTOK * KV_ * 64;
        apply_rope_kernel<<<(totk + 255) / 256, 256>>>(k, KV_, totk);
    }

    // 3) attention
    {
        dim3 ga(S_ / BQ, H_, B_);
        attn_kernel<<<ga, 256, attn_smem>>>(q, k, v, o);
    }

    // 4) output projection (naive GEMM)
    {
        dim3 go((E_ + 31) / 32, (NTOK + 7) / 8);
        ngemm_kernel<<<go, 256>>>(o, Wo, out, NTOK, E_, E_);
    }
}

// round 4
// speedup vs baseline: 3.1087x; 3.1087x over previous
#include <cuda_runtime.h>
#include <cuda_bf16.h>
#include <math.h>

// Problem constants
#define B_  2
#define S_  2048
#define E_  2048
#define H_  16
#define KV_ 4
#define G_  (H_ / KV_)   // 4
#define D_  128
#define NTOK (B_ * S_)   // 4096

// Scratch (device globals: allocation-free rule)
__device__ float g_q[NTOK * (H_ * D_)];   // [4096, 2048]
__device__ float g_k[NTOK * (KV_ * D_)];  // [4096, 512]
__device__ float g_v[NTOK * (KV_ * D_)];  // [4096, 512]
__device__ float g_o[NTOK * (H_ * D_)];   // [4096, 2048]
__device__ float g_cos[S_ * 64];          // rope tables
__device__ float g_sin[S_ * 64];

// ---------------------------------------------------------------------------
// Tiled SGEMM: C[M,N] = A[M,K] @ B[K,N], row-major. M%128==0, N%128==0, K%16==0.
// 128x128 block tile, 8x8 register microtile, BK=16.
// ---------------------------------------------------------------------------
#define BM 128
#define BN 128
#define BKK 16

__global__ void __launch_bounds__(256)
sgemm_kernel(const float* __restrict__ A, const float* __restrict__ Bm,
             float* __restrict__ C, int M, int N, int K) {
    __shared__ float As[BKK][BM];
    __shared__ float Bs[BKK][BN];

    const int t = threadIdx.x;
    const int block_m = blockIdx.y * BM;
    const int block_n = blockIdx.x * BN;

    const int arow = t >> 2;            // 0..63 (2 iters, +64)
    const int acol = (t & 3) << 2;      // 0,4,8,12
    const int brow = t >> 5;            // 0..7 (2 iters, +8)
    const int bcol = (t & 31) << 2;     // 0..124
    const int tr = (t >> 4) << 3;
    const int tc = (t & 15) << 3;

    float acc[8][8];
#pragma unroll
    for (int i = 0; i < 8; i++)
#pragma unroll
        for (int j = 0; j < 8; j++) acc[i][j] = 0.f;

    for (int k0 = 0; k0 < K; k0 += BKK) {
#pragma unroll
        for (int it = 0; it < 2; it++) {
            int r = arow + it * 64;
            float4 v = *(const float4*)&A[(size_t)(block_m + r) * K + k0 + acol];
            As[acol + 0][r] = v.x;
            As[acol + 1][r] = v.y;
            As[acol + 2][r] = v.z;
            As[acol + 3][r] = v.w;
        }
#pragma unroll
        for (int it = 0; it < 2; it++) {
            int r = brow + it * 8;
            *(float4*)&Bs[r][bcol] =
                *(const float4*)&Bm[(size_t)(k0 + r) * N + block_n + bcol];
        }
        __syncthreads();

#pragma unroll
        for (int k = 0; k < BKK; k++) {
            float ra[8], rb[8];
#pragma unroll
            for (int i = 0; i < 8; i++) ra[i] = As[k][tr + i];
#pragma unroll
            for (int j = 0; j < 8; j++) rb[j] = Bs[k][tc + j];
#pragma unroll
            for (int i = 0; i < 8; i++)
#pragma unroll
                for (int j = 0; j < 8; j++) acc[i][j] += ra[i] * rb[j];
        }
        __syncthreads();
    }

#pragma unroll
    for (int i = 0; i < 8; i++) {
#pragma unroll
        for (int j = 0; j < 8; j += 4) {
            float4 v = make_float4(acc[i][j], acc[i][j + 1], acc[i][j + 2], acc[i][j + 3]);
            *(float4*)&C[(size_t)(block_m + tr + i) * N + block_n + tc + j] = v;
        }
    }
}

// ---------------------------------------------------------------------------
// RoPE tables (double precision build): cos/sin[s][i] for angle s*10000^(-i/64)
// ---------------------------------------------------------------------------
__global__ void build_tables_kernel() {
    int idx = blockIdx.x * blockDim.x + threadIdx.x;
    if (idx >= S_ * 64) return;
    int i = idx & 63;
    int s = idx >> 6;
    double inv = pow(10000.0, -(double)i / 64.0);
    double ang = (double)s * inv;
    g_cos[idx] = (float)cos(ang);
    g_sin[idx] = (float)sin(ang);
}

// Apply rope in place. p: [NTOK, nheads*128].
__global__ void apply_rope_kernel(float* __restrict__ p, int nheads, int total) {
    int idx = blockIdx.x * blockDim.x + threadIdx.x;
    if (idx >= total) return;
    int i = idx & 63;
    int h = (idx >> 6) % nheads;
    int tok = idx / (nheads * 64);
    int s = tok & (S_ - 1);

    float c  = g_cos[s * 64 + i];
    float sn = g_sin[s * 64 + i];

    size_t base = (size_t)tok * (nheads * 128) + h * 128;
    float x1 = p[base + i];
    float x2 = p[base + 64 + i];
    p[base + i]      = x1 * c - x2 * sn;
    p[base + 64 + i] = x2 * c + x1 * sn;
}

// ---------------------------------------------------------------------------
// Flash attention (causal, online softmax), fp32, smem-staged probabilities.
// grid: (S/64, H, B), block 256 (8 warps). Warp w owns rows w*8..w*8+7.
// Lane owns output dims [lane*4, lane*4+4).
// ---------------------------------------------------------------------------
#define BQ 64
#define BKV 32
#define KS_STRIDE 132
#define SP_STRIDE 33

__global__ void __launch_bounds__(256)
attn_kernel(const float* __restrict__ q, const float* __restrict__ k,
            const float* __restrict__ v, float* __restrict__ o) {
    extern __shared__ float sm[];
    float* Qs  = sm;                         // [64][128]
    float* Ks  = Qs + BQ * 128;              // [32][132]
    float* Vs  = Ks + BKV * KS_STRIDE;       // [32][128]
    float* Sp  = Vs + BKV * 128;             // [64][33]
    float* m_s = Sp + BQ * SP_STRIDE;        // [64]
    float* l_s = m_s + BQ;                   // [64]
    float* c_s = l_s + BQ;                   // [64]

    const int qt = blockIdx.x, h = blockIdx.y, b = blockIdx.z;
    const int kvh = h >> 2;
    const int t = threadIdx.x, warp = t >> 5, lane = t & 31;
    const int q0 = qt * BQ;
    const int row0 = warp * 8;
    const float scale = 0.08838834764831845f;

    const float* qb = q + (size_t)(b * S_ + q0) * (H_ * D_) + h * D_;
    for (int i = t; i < BQ * 32; i += 256) {
        int r = i >> 5, c = (i & 31) << 2;
        *(float4*)(Qs + r * 128 + c) = *(const float4*)(qb + (size_t)r * (H_ * D_) + c);
    }
    if (t < BQ) { m_s[t] = -INFINITY; l_s[t] = 0.f; }

    float acc[8][4];
#pragma unroll
    for (int r = 0; r < 8; r++)
#pragma unroll
        for (int u = 0; u < 4; u++) acc[r][u] = 0.f;
    __syncthreads();

    for (int ks0 = 0; ks0 < q0 + BQ; ks0 += BKV) {
        const float* kb = k + (size_t)(b * S_ + ks0) * (KV_ * D_) + kvh * D_;
        const float* vb = v + (size_t)(b * S_ + ks0) * (KV_ * D_) + kvh * D_;
        for (int i = t; i < BKV * 32; i += 256) {
            int r = i >> 5, c = (i & 31) << 2;
            *(float4*)(Ks + r * KS_STRIDE + c) = *(const float4*)(kb + (size_t)r * (KV_ * D_) + c);
            *(float4*)(Vs + r * 128 + c)       = *(const float4*)(vb + (size_t)r * (KV_ * D_) + c);
        }
        __syncthreads();

        const int kpos = ks0 + lane;
#pragma unroll
        for (int r = 0; r < 8; r++) {
            float s = 0.f;
#pragma unroll
            for (int d4 = 0; d4 < 32; d4++) {
                float4 kd = *(const float4*)(Ks + lane * KS_STRIDE + d4 * 4);
                float4 qd = *(const float4*)(Qs + (row0 + r) * 128 + d4 * 4);
                s = fmaf(qd.x, kd.x, s);
                s = fmaf(qd.y, kd.y, s);
                s = fmaf(qd.z, kd.z, s);
                s = fmaf(qd.w, kd.w, s);
            }
            int qpos = q0 + row0 + r;
            Sp[(row0 + r) * SP_STRIDE + lane] = (kpos <= qpos) ? s * scale : -INFINITY;
        }
        __syncthreads();

        if (t < BQ) {
            float* sp = Sp + t * SP_STRIDE;
            float mold = m_s[t];
            float mloc = -INFINITY;
#pragma unroll
            for (int j = 0; j < BKV; j++) mloc = fmaxf(mloc, sp[j]);
            float mn = fmaxf(mold, mloc);
            float corr = expf(mold - mn);
            float sum = 0.f;
#pragma unroll
            for (int j = 0; j < BKV; j++) {
                float pj = expf(sp[j] - mn);
                sp[j] = pj;
                sum += pj;
            }
            l_s[t] = l_s[t] * corr + sum;
            m_s[t] = mn;
            c_s[t] = corr;
        }
        __syncthreads();

#pragma unroll
        for (int r = 0; r < 8; r++) {
            float corr = c_s[row0 + r];
#pragma unroll
            for (int u = 0; u < 4; u++) acc[r][u] *= corr;
        }
#pragma unroll 4
        for (int j = 0; j < BKV; j++) {
            float4 vv = *(const float4*)(Vs + j * 128 + lane * 4);
#pragma unroll
            for (int r = 0; r < 8; r++) {
                float pb = Sp[(row0 + r) * SP_STRIDE + j];
                acc[r][0] = fmaf(pb, vv.x, acc[r][0]);
                acc[r][1] = fmaf(pb, vv.y, acc[r][1]);
                acc[r][2] = fmaf(pb, vv.z, acc[r][2]);
                acc[r][3] = fmaf(pb, vv.w, acc[r][3]);
            }
        }
        __syncthreads();
    }

#pragma unroll
    for (int r = 0; r < 8; r++) {
        float inv = 1.f / l_s[row0 + r];
        float* ob = o + (size_t)(b * S_ + q0 + row0 + r) * (H_ * D_) + h * D_;
        float4 ov = make_float4(acc[r][0] * inv, acc[r][1] * inv,
                                acc[r][2] * inv, acc[r][3] * inv);
        *(float4*)(ob + lane * 4) = ov;
    }
}

// ---------------------------------------------------------------------------
// Launch
// ---------------------------------------------------------------------------
extern "C" void kernel_launch(void* const* d_in, const int* in_sizes, int n_in,
                              void* d_out, int out_size) {
    // Input mapping via element counts (harness passes alphabetical order).
    // dict order:         x=8388608, Wq, Wk, Wv, Wo
    // alphabetical order: Wk, Wo, Wq, Wv, x
    const float *x, *Wq, *Wk, *Wv, *Wo;
    if (in_sizes[0] == NTOK * E_) {
        x  = (const float*)d_in[0];
        Wq = (const float*)d_in[1];
        Wk = (const float*)d_in[2];
        Wv = (const float*)d_in[3];
        Wo = (const float*)d_in[4];
    } else {
        Wk = (const float*)d_in[0];
        Wo = (const float*)d_in[1];
        Wq = (const float*)d_in[2];
        Wv = (const float*)d_in[3];
        x  = (const float*)d_in[4];
    }
    float* out = (float*)d_out;

    float *q, *k, *v, *o;
    cudaGetSymbolAddress((void**)&q, g_q);
    cudaGetSymbolAddress((void**)&k, g_k);
    cudaGetSymbolAddress((void**)&v, g_v);
    cudaGetSymbolAddress((void**)&o, g_o);

    const int attn_smem =
        (BQ * 128 + BKV * KS_STRIDE + BKV * 128 + BQ * SP_STRIDE + 3 * BQ) * (int)sizeof(float);
    cudaFuncSetAttribute(attn_kernel, cudaFuncAttributeMaxDynamicSharedMemorySize, attn_smem);

    // 0) rope tables
    build_tables_kernel<<<(S_ * 64 + 255) / 256, 256>>>();

    // 1) projections (tiled SGEMM)
    {
        dim3 gq(E_ / BN, NTOK / BM);
        sgemm_kernel<<<gq, 256>>>(x, Wq, q, NTOK, H_ * D_, E_);
        dim3 gk((KV_ * D_) / BN, NTOK / BM);
        sgemm_kernel<<<gk, 256>>>(x, Wk, k, NTOK, KV_ * D_, E_);
        sgemm_kernel<<<gk, 256>>>(x, Wv, v, NTOK, KV_ * D_, E_);
    }

    // 2) RoPE (in place, table-based)
    {
        int totq = NTOK * H_ * 64;
        apply_rope_kernel<<<(totq + 255) / 256, 256>>>(q, H_, totq);
        int totk = NTOK * KV_ * 64;
        apply_rope_kernel<<<(totk + 255) / 256, 256>>>(k, KV_, totk);
    }

    // 3) attention
    {
        dim3 ga(S_ / BQ, H_, B_);
        attn_kernel<<<ga, 256, attn_smem>>>(q, k, v, o);
    }

    // 4) output projection (tiled SGEMM)
    {
        dim3 go(E_ / BN, NTOK / BM);
        sgemm_kernel<<<go, 256>>>(o, Wo, out, NTOK, E_, E_);
    }
}

// round 6
// speedup vs baseline: 4.8768x; 1.5688x over previous
#include <cuda_runtime.h>
#include <cuda_bf16.h>
#include <math.h>
#include <stdint.h>

// Problem constants
#define B_  2
#define S_  2048
#define E_  2048
#define H_  16
#define KV_ 4
#define G_  (H_ / KV_)   // 4
#define D_  128
#define NTOK (B_ * S_)   // 4096

// ---------------------------------------------------------------------------
// Scratch (device globals: allocation-free rule)
// ---------------------------------------------------------------------------
__device__ float g_q[NTOK * (H_ * D_)];
__device__ float g_k[NTOK * (KV_ * D_)];
__device__ float g_v[NTOK * (KV_ * D_)];
__device__ float g_o[NTOK * (H_ * D_)];
__device__ float g_cos[S_ * 64];
__device__ float g_sin[S_ * 64];

// bf16 split operands
__device__ __nv_bfloat16 g_xh[NTOK * E_];
__device__ __nv_bfloat16 g_xl[NTOK * E_];
__device__ __nv_bfloat16 g_oh[NTOK * (H_ * D_)];
__device__ __nv_bfloat16 g_ol[NTOK * (H_ * D_)];
// transposed weights [N][K] (K-major), hi/lo
__device__ __nv_bfloat16 g_Wqt_h[(H_ * D_) * E_];
__device__ __nv_bfloat16 g_Wqt_l[(H_ * D_) * E_];
__device__ __nv_bfloat16 g_Wkt_h[(KV_ * D_) * E_];
__device__ __nv_bfloat16 g_Wkt_l[(KV_ * D_) * E_];
__device__ __nv_bfloat16 g_Wvt_h[(KV_ * D_) * E_];
__device__ __nv_bfloat16 g_Wvt_l[(KV_ * D_) * E_];
__device__ __nv_bfloat16 g_Wot_h[E_ * E_];
__device__ __nv_bfloat16 g_Wot_l[E_ * E_];

// ---------------------------------------------------------------------------
// Baseline-ISA tensor-core helpers (sm_80-era PTX, works on plain sm_103)
// ---------------------------------------------------------------------------
__device__ __forceinline__ uint32_t smem_u32(const void* p) {
    uint32_t a;
    asm("{ .reg .u64 t; cvta.to.shared.u64 t, %1; cvt.u32.u64 %0, t; }" : "=r"(a) : "l"(p));
    return a;
}

__device__ __forceinline__ void ldsm4(uint32_t* r, uint32_t addr) {
    asm volatile("ldmatrix.sync.aligned.m8n8.x4.shared.b16 {%0,%1,%2,%3}, [%4];"
                 : "=r"(r[0]), "=r"(r[1]), "=r"(r[2]), "=r"(r[3]) : "r"(addr));
}

__device__ __forceinline__ void mma16816(float* d, const uint32_t* a, const uint32_t* b) {
    asm volatile(
        "mma.sync.aligned.m16n8k16.row.col.f32.bf16.bf16.f32 "
        "{%0,%1,%2,%3}, {%4,%5,%6,%7}, {%8,%9}, {%0,%1,%2,%3};"
        : "+f"(d[0]), "+f"(d[1]), "+f"(d[2]), "+f"(d[3])
        : "r"(a[0]), "r"(a[1]), "r"(a[2]), "r"(a[3]), "r"(b[0]), "r"(b[1]));
}

#define CP16(dst, src) \
    asm volatile("cp.async.cg.shared.global [%0], [%1], 16;" :: "r"(dst), "l"(src))
#define CP_COMMIT() asm volatile("cp.async.commit_group;" ::: "memory")
#define CP_WAIT0() asm volatile("cp.async.wait_group 0;" ::: "memory")
#define CP_WAIT1() asm volatile("cp.async.wait_group 1;" ::: "memory")

// Swizzled smem byte offset within a [128 rows][64 bytes] tile.
// 16B chunk index XORed with (row>>1)&3 -> conflict-free ldmatrix phases.
__device__ __forceinline__ uint32_t swz(int row, int chunk) {
    return (uint32_t)(row * 64 + ((chunk ^ ((row >> 1) & 3)) << 4));
}

// ---------------------------------------------------------------------------
// bf16-split tensor-core GEMM: C[M,N] = A[M,K] @ Bt[N,K]^T  (fp32 result)
// A,Bt given as hi/lo bf16, K-major. CTA tile 128x128, BK=32, double-buffered
// cp.async pipeline. 3 split-term MMAs (hh, hl, lh).
// ---------------------------------------------------------------------------
#define BKC 32
#define TILE_B 8192                 // 128 rows * 64 bytes
#define BUF_B (4 * TILE_B)          // Ah, Al, Bh, Bl
#define BFG_SMEM (2 * BUF_B)        // 64 KB

__global__ void __launch_bounds__(256, 1)
bfgemm_kernel(const __nv_bfloat16* __restrict__ Ah, const __nv_bfloat16* __restrict__ Al,
              const __nv_bfloat16* __restrict__ Bh, const __nv_bfloat16* __restrict__ Bl,
              float* __restrict__ C, int M, int N, int K) {
    extern __shared__ char smem[];
    const uint32_t smem_base = smem_u32(smem);
    const int t = threadIdx.x;
    const int lane = t & 31;
    const int wid = t >> 5;
    const int wm = wid & 1;          // 2 x 64 rows
    const int wn = wid >> 1;         // 4 x 32 cols
    const int bm = blockIdx.y * 128;
    const int bn = blockIdx.x * 128;

    const char* srcs[4] = {
        (const char*)(Ah + (size_t)bm * K),
        (const char*)(Al + (size_t)bm * K),
        (const char*)(Bh + (size_t)bn * K),
        (const char*)(Bl + (size_t)bn * K) };

    float acc[4][4][4];
#pragma unroll
    for (int i = 0; i < 4; i++)
#pragma unroll
        for (int j = 0; j < 4; j++)
#pragma unroll
            for (int u = 0; u < 4; u++) acc[i][j][u] = 0.f;

    const int NC = K / BKC;
    const size_t rowb = (size_t)K * 2;   // bytes per gmem row

    // prologue: load chunk 0
    {
        uint32_t sbase = smem_base;
#pragma unroll
        for (int tl = 0; tl < 4; tl++) {
            const char* src = srcs[tl];
            uint32_t dstt = sbase + tl * TILE_B;
#pragma unroll
            for (int j = 0; j < 2; j++) {
                int idx = t + j * 256;
                int r = idx >> 2, c = idx & 3;
                CP16(dstt + swz(r, c), src + (size_t)r * rowb + c * 16);
            }
        }
        CP_COMMIT();
    }

    for (int ic = 0; ic < NC; ic++) {
        if (ic + 1 < NC) {
            const int k0b = (ic + 1) * BKC * 2;
            uint32_t sbase = smem_base + ((ic + 1) & 1) * BUF_B;
#pragma unroll
            for (int tl = 0; tl < 4; tl++) {
                const char* src = srcs[tl] + k0b;
                uint32_t dstt = sbase + tl * TILE_B;
#pragma unroll
                for (int j = 0; j < 2; j++) {
                    int idx = t + j * 256;
                    int r = idx >> 2, c = idx & 3;
                    CP16(dstt + swz(r, c), src + (size_t)r * rowb + c * 16);
                }
            }
            CP_COMMIT();
            CP_WAIT1();
        } else {
            CP_WAIT0();
        }
        __syncthreads();

        const uint32_t buf = smem_base + (ic & 1) * BUF_B;
        const uint32_t a_h_base = buf;
        const uint32_t a_l_base = buf + TILE_B;
        const uint32_t b_h_base = buf + 2 * TILE_B;
        const uint32_t b_l_base = buf + 3 * TILE_B;

#pragma unroll
        for (int ks = 0; ks < 2; ks++) {
            uint32_t a_h[4][4], a_l[4][4];
#pragma unroll
            for (int mt = 0; mt < 4; mt++) {
                int row = wm * 64 + mt * 16 + (lane & 15);
                int chunk = ks * 2 + (lane >> 4);
                uint32_t off = swz(row, chunk);
                ldsm4(a_h[mt], a_h_base + off);
                ldsm4(a_l[mt], a_l_base + off);
            }
            uint32_t b_h[4][2], b_l[4][2];
#pragma unroll
            for (int np = 0; np < 2; np++) {
                int row = wn * 32 + np * 16 + ((lane >> 4) << 3) + (lane & 7);
                int chunk = ks * 2 + ((lane >> 3) & 1);
                uint32_t off = swz(row, chunk);
                uint32_t r4[4];
                ldsm4(r4, b_h_base + off);
                b_h[np * 2][0] = r4[0]; b_h[np * 2][1] = r4[1];
                b_h[np * 2 + 1][0] = r4[2]; b_h[np * 2 + 1][1] = r4[3];
                ldsm4(r4, b_l_base + off);
                b_l[np * 2][0] = r4[0]; b_l[np * 2][1] = r4[1];
                b_l[np * 2 + 1][0] = r4[2]; b_l[np * 2 + 1][1] = r4[3];
            }
#pragma unroll
            for (int mt = 0; mt < 4; mt++)
#pragma unroll
                for (int nt = 0; nt < 4; nt++) {
                    mma16816(acc[mt][nt], a_h[mt], b_h[nt]);
                    mma16816(acc[mt][nt], a_h[mt], b_l[nt]);
                    mma16816(acc[mt][nt], a_l[mt], b_h[nt]);
                }
        }
        __syncthreads();
    }

    // Epilogue
#pragma unroll
    for (int mt = 0; mt < 4; mt++) {
#pragma unroll
        for (int nt = 0; nt < 4; nt++) {
            int r0 = bm + wm * 64 + mt * 16 + (lane >> 2);
            int col = bn + wn * 32 + nt * 8 + ((lane & 3) << 1);
            float* p0 = C + (size_t)r0 * N + col;
            float* p1 = C + (size_t)(r0 + 8) * N + col;
            p0[0] = acc[mt][nt][0]; p0[1] = acc[mt][nt][1];
            p1[0] = acc[mt][nt][2]; p1[1] = acc[mt][nt][3];
        }
    }
}

// ---------------------------------------------------------------------------
// Conversion kernels
// ---------------------------------------------------------------------------
__global__ void conv_split_kernel(const float* __restrict__ A,
                                  __nv_bfloat16* __restrict__ Ahi,
                                  __nv_bfloat16* __restrict__ Alo, int total) {
    int i = blockIdx.x * blockDim.x + threadIdx.x;
    if (i >= total) return;
    float v = A[i];
    __nv_bfloat16 h = __float2bfloat16(v);
    float lo = v - __bfloat162float(h);
    Ahi[i] = h;
    Alo[i] = __float2bfloat16(lo);
}

// Transpose + split: W[K][N] fp32 -> Th[N][K], Tl[N][K] bf16
__global__ void conv_transpose_kernel(const float* __restrict__ W,
                                      __nv_bfloat16* __restrict__ Th,
                                      __nv_bfloat16* __restrict__ Tl, int K, int N) {
    __shared__ float tile[32][33];
    int n0 = blockIdx.x * 32, k0 = blockIdx.y * 32;
    int tx = threadIdx.x & 31, ty = threadIdx.x >> 5;
#pragma unroll
    for (int i = 0; i < 32; i += 8)
        tile[ty + i][tx] = W[(size_t)(k0 + ty + i) * N + n0 + tx];
    __syncthreads();
#pragma unroll
    for (int i = 0; i < 32; i += 8) {
        float v = tile[tx][ty + i];
        __nv_bfloat16 h = __float2bfloat16(v);
        float lo = v - __bfloat162float(h);
        size_t o = (size_t)(n0 + ty + i) * K + k0 + tx;
        Th[o] = h;
        Tl[o] = __float2bfloat16(lo);
    }
}

// ---------------------------------------------------------------------------
// RoPE tables + apply
// ---------------------------------------------------------------------------
__global__ void build_tables_kernel() {
    int idx = blockIdx.x * blockDim.x + threadIdx.x;
    if (idx >= S_ * 64) return;
    int i = idx & 63;
    int s = idx >> 6;
    double inv = pow(10000.0, -(double)i / 64.0);
    double ang = (double)s * inv;
    g_cos[idx] = (float)cos(ang);
    g_sin[idx] = (float)sin(ang);
}

__global__ void apply_rope_kernel(float* __restrict__ p, int nheads, int total) {
    int idx = blockIdx.x * blockDim.x + threadIdx.x;
    if (idx >= total) return;
    int i = idx & 63;
    int h = (idx >> 6) % nheads;
    int tok = idx / (nheads * 64);
    int s = tok & (S_ - 1);

    float c  = g_cos[s * 64 + i];
    float sn = g_sin[s * 64 + i];

    size_t base = (size_t)tok * (nheads * 128) + h * 128;
    float x1 = p[base + i];
    float x2 = p[base + 64 + i];
    p[base + i]      = x1 * c - x2 * sn;
    p[base + 64 + i] = x2 * c + x1 * sn;
}

// ---------------------------------------------------------------------------
// Flash attention (causal, online softmax), fp32, smem-staged (validated R3/R4)
// ---------------------------------------------------------------------------
#define BQ 64
#define BKV 32
#define KS_STRIDE 132
#define SP_STRIDE 33

__global__ void __launch_bounds__(256)
attn_kernel(const float* __restrict__ q, const float* __restrict__ k,
            const float* __restrict__ v, float* __restrict__ o) {
    extern __shared__ float sm[];
    float* Qs  = sm;
    float* Ks  = Qs + BQ * 128;
    float* Vs  = Ks + BKV * KS_STRIDE;
    float* Sp  = Vs + BKV * 128;
    float* m_s = Sp + BQ * SP_STRIDE;
    float* l_s = m_s + BQ;
    float* c_s = l_s + BQ;

    const int qt = blockIdx.x, h = blockIdx.y, b = blockIdx.z;
    const int kvh = h >> 2;
    const int t = threadIdx.x, warp = t >> 5, lane = t & 31;
    const int q0 = qt * BQ;
    const int row0 = warp * 8;
    const float scale = 0.08838834764831845f;

    const float* qb = q + (size_t)(b * S_ + q0) * (H_ * D_) + h * D_;
    for (int i = t; i < BQ * 32; i += 256) {
        int r = i >> 5, c = (i & 31) << 2;
        *(float4*)(Qs + r * 128 + c) = *(const float4*)(qb + (size_t)r * (H_ * D_) + c);
    }
    if (t < BQ) { m_s[t] = -INFINITY; l_s[t] = 0.f; }

    float acc[8][4];
#pragma unroll
    for (int r = 0; r < 8; r++)
#pragma unroll
        for (int u = 0; u < 4; u++) acc[r][u] = 0.f;
    __syncthreads();

    for (int ks0 = 0; ks0 < q0 + BQ; ks0 += BKV) {
        const float* kb = k + (size_t)(b * S_ + ks0) * (KV_ * D_) + kvh * D_;
        const float* vb = v + (size_t)(b * S_ + ks0) * (KV_ * D_) + kvh * D_;
        for (int i = t; i < BKV * 32; i += 256) {
            int r = i >> 5, c = (i & 31) << 2;
            *(float4*)(Ks + r * KS_STRIDE + c) = *(const float4*)(kb + (size_t)r * (KV_ * D_) + c);
            *(float4*)(Vs + r * 128 + c)       = *(const float4*)(vb + (size_t)r * (KV_ * D_) + c);
        }
        __syncthreads();

        const int kpos = ks0 + lane;
#pragma unroll
        for (int r = 0; r < 8; r++) {
            float s = 0.f;
#pragma unroll
            for (int d4 = 0; d4 < 32; d4++) {
                float4 kd = *(const float4*)(Ks + lane * KS_STRIDE + d4 * 4);
                float4 qd = *(const float4*)(Qs + (row0 + r) * 128 + d4 * 4);
                s = fmaf(qd.x, kd.x, s);
                s = fmaf(qd.y, kd.y, s);
                s = fmaf(qd.z, kd.z, s);
                s = fmaf(qd.w, kd.w, s);
            }
            int qpos = q0 + row0 + r;
            Sp[(row0 + r) * SP_STRIDE + lane] = (kpos <= qpos) ? s * scale : -INFINITY;
        }
        __syncthreads();

        if (t < BQ) {
            float* sp = Sp + t * SP_STRIDE;
            float mold = m_s[t];
            float mloc = -INFINITY;
#pragma unroll
            for (int j = 0; j < BKV; j++) mloc = fmaxf(mloc, sp[j]);
            float mn = fmaxf(mold, mloc);
            float corr = expf(mold - mn);
            float sum = 0.f;
#pragma unroll
            for (int j = 0; j < BKV; j++) {
                float pj = expf(sp[j] - mn);
                sp[j] = pj;
                sum += pj;
            }
            l_s[t] = l_s[t] * corr + sum;
            m_s[t] = mn;
            c_s[t] = corr;
        }
        __syncthreads();

#pragma unroll
        for (int r = 0; r < 8; r++) {
            float corr = c_s[row0 + r];
#pragma unroll
            for (int u = 0; u < 4; u++) acc[r][u] *= corr;
        }
#pragma unroll 4
        for (int j = 0; j < BKV; j++) {
            float4 vv = *(const float4*)(Vs + j * 128 + lane * 4);
#pragma unroll
            for (int r = 0; r < 8; r++) {
                float pb = Sp[(row0 + r) * SP_STRIDE + j];
                acc[r][0] = fmaf(pb, vv.x, acc[r][0]);
                acc[r][1] = fmaf(pb, vv.y, acc[r][1]);
                acc[r][2] = fmaf(pb, vv.z, acc[r][2]);
                acc[r][3] = fmaf(pb, vv.w, acc[r][3]);
            }
        }
        __syncthreads();
    }

#pragma unroll
    for (int r = 0; r < 8; r++) {
        float inv = 1.f / l_s[row0 + r];
        float* ob = o + (size_t)(b * S_ + q0 + row0 + r) * (H_ * D_) + h * D_;
        float4 ov = make_float4(acc[r][0] * inv, acc[r][1] * inv,
                                acc[r][2] * inv, acc[r][3] * inv);
        *(float4*)(ob + lane * 4) = ov;
    }
}

// ---------------------------------------------------------------------------
// Launch
// ---------------------------------------------------------------------------
extern "C" void kernel_launch(void* const* d_in, const int* in_sizes, int n_in,
                              void* d_out, int out_size) {
    const float *x, *Wq, *Wk, *Wv, *Wo;
    if (in_sizes[0] == NTOK * E_) {
        x  = (const float*)d_in[0];
        Wq = (const float*)d_in[1];
        Wk = (const float*)d_in[2];
        Wv = (const float*)d_in[3];
        Wo = (const float*)d_in[4];
    } else {
        Wk = (const float*)d_in[0];
        Wo = (const float*)d_in[1];
        Wq = (const float*)d_in[2];
        Wv = (const float*)d_in[3];
        x  = (const float*)d_in[4];
    }
    float* out = (float*)d_out;

    float *q, *k, *v, *o;
    cudaGetSymbolAddress((void**)&q, g_q);
    cudaGetSymbolAddress((void**)&k, g_k);
    cudaGetSymbolAddress((void**)&v, g_v);
    cudaGetSymbolAddress((void**)&o, g_o);
    __nv_bfloat16 *xh, *xl, *oh, *ol;
    cudaGetSymbolAddress((void**)&xh, g_xh);
    cudaGetSymbolAddress((void**)&xl, g_xl);
    cudaGetSymbolAddress((void**)&oh, g_oh);
    cudaGetSymbolAddress((void**)&ol, g_ol);
    __nv_bfloat16 *Wqt_h, *Wqt_l, *Wkt_h, *Wkt_l, *Wvt_h, *Wvt_l, *Wot_h, *Wot_l;
    cudaGetSymbolAddress((void**)&Wqt_h, g_Wqt_h);
    cudaGetSymbolAddress((void**)&Wqt_l, g_Wqt_l);
    cudaGetSymbolAddress((void**)&Wkt_h, g_Wkt_h);
    cudaGetSymbolAddress((void**)&Wkt_l, g_Wkt_l);
    cudaGetSymbolAddress((void**)&Wvt_h, g_Wvt_h);
    cudaGetSymbolAddress((void**)&Wvt_l, g_Wvt_l);
    cudaGetSymbolAddress((void**)&Wot_h, g_Wot_h);
    cudaGetSymbolAddress((void**)&Wot_l, g_Wot_l);

    const int attn_smem =
        (BQ * 128 + BKV * KS_STRIDE + BKV * 128 + BQ * SP_STRIDE + 3 * BQ) * (int)sizeof(float);
    cudaFuncSetAttribute(attn_kernel, cudaFuncAttributeMaxDynamicSharedMemorySize, attn_smem);
    cudaFuncSetAttribute(bfgemm_kernel, cudaFuncAttributeMaxDynamicSharedMemorySize, BFG_SMEM);

    // 0) rope tables
    build_tables_kernel<<<(S_ * 64 + 255) / 256, 256>>>();

    // 1) convert inputs: split x; transpose+split weights
    conv_split_kernel<<<(NTOK * E_ + 255) / 256, 256>>>(x, xh, xl, NTOK * E_);
    {
        dim3 gq((H_ * D_) / 32, E_ / 32);
        conv_transpose_kernel<<<gq, 256>>>(Wq, Wqt_h, Wqt_l, E_, H_ * D_);
        dim3 gk((KV_ * D_) / 32, E_ / 32);
        conv_transpose_kernel<<<gk, 256>>>(Wk, Wkt_h, Wkt_l, E_, KV_ * D_);
        conv_transpose_kernel<<<gk, 256>>>(Wv, Wvt_h, Wvt_l, E_, KV_ * D_);
        dim3 go(E_ / 32, E_ / 32);
        conv_transpose_kernel<<<go, 256>>>(Wo, Wot_h, Wot_l, E_, E_);
    }

    // 2) projections (mma.sync bf16-split GEMM)
    {
        dim3 gq((H_ * D_) / 128, NTOK / 128);
        bfgemm_kernel<<<gq, 256, BFG_SMEM>>>(xh, xl, Wqt_h, Wqt_l, q, NTOK, H_ * D_, E_);
        dim3 gk((KV_ * D_) / 128, NTOK / 128);
        bfgemm_kernel<<<gk, 256, BFG_SMEM>>>(xh, xl, Wkt_h, Wkt_l, k, NTOK, KV_ * D_, E_);
        bfgemm_kernel<<<gk, 256, BFG_SMEM>>>(xh, xl, Wvt_h, Wvt_l, v, NTOK, KV_ * D_, E_);
    }

    // 3) RoPE (in place)
    {
        int totq = NTOK * H_ * 64;
        apply_rope_kernel<<<(totq + 255) / 256, 256>>>(q, H_, totq);
        int totk = NTOK * KV_ * 64;
        apply_rope_kernel<<<(totk + 255) / 256, 256>>>(k, KV_, totk);
    }

    // 4) attention
    {
        dim3 ga(S_ / BQ, H_, B_);
        attn_kernel<<<ga, 256, attn_smem>>>(q, k, v, o);
    }

    // 5) output projection
    conv_split_kernel<<<(NTOK * (H_ * D_) + 255) / 256, 256>>>(o, oh, ol, NTOK * (H_ * D_));
    {
        dim3 go(E_ / 128, NTOK / 128);
        bfgemm_kernel<<<go, 256, BFG_SMEM>>>(oh, ol, Wot_h, Wot_l, out, NTOK, E_, E_);
    }
}

// round 7
// speedup vs baseline: 9.9475x; 2.0397x over previous
#include <cuda_runtime.h>
#include <cuda_bf16.h>
#include <math.h>
#include <stdint.h>

// Problem constants
#define B_  2
#define S_  2048
#define E_  2048
#define H_  16
#define KV_ 4
#define G_  (H_ / KV_)   // 4
#define D_  128
#define NTOK (B_ * S_)   // 4096

// ---------------------------------------------------------------------------
// Scratch (device globals)
// ---------------------------------------------------------------------------
__device__ float g_q[NTOK * (H_ * D_)];
__device__ float g_k[NTOK * (KV_ * D_)];
__device__ float g_v[NTOK * (KV_ * D_)];
__device__ float g_cos[S_ * 64];
__device__ float g_sin[S_ * 64];

__device__ __nv_bfloat16 g_xh[NTOK * E_];
__device__ __nv_bfloat16 g_xl[NTOK * E_];
__device__ __nv_bfloat16 g_oh[NTOK * (H_ * D_)];
__device__ __nv_bfloat16 g_ol[NTOK * (H_ * D_)];
// post-rope bf16 operands
__device__ __nv_bfloat16 g_qbh[NTOK * (H_ * D_)];
__device__ __nv_bfloat16 g_qbl[NTOK * (H_ * D_)];
__device__ __nv_bfloat16 g_kbh[NTOK * (KV_ * D_)];
__device__ __nv_bfloat16 g_kbl[NTOK * (KV_ * D_)];
// V transposed: [(b*KV+kvh)*128 + d][s]
__device__ __nv_bfloat16 g_vth[B_ * KV_ * D_ * S_];
__device__ __nv_bfloat16 g_vtl[B_ * KV_ * D_ * S_];
// transposed weights [N][K], hi/lo
__device__ __nv_bfloat16 g_Wqt_h[(H_ * D_) * E_];
__device__ __nv_bfloat16 g_Wqt_l[(H_ * D_) * E_];
__device__ __nv_bfloat16 g_Wkt_h[(KV_ * D_) * E_];
__device__ __nv_bfloat16 g_Wkt_l[(KV_ * D_) * E_];
__device__ __nv_bfloat16 g_Wvt_h[(KV_ * D_) * E_];
__device__ __nv_bfloat16 g_Wvt_l[(KV_ * D_) * E_];
__device__ __nv_bfloat16 g_Wot_h[E_ * E_];
__device__ __nv_bfloat16 g_Wot_l[E_ * E_];

// ---------------------------------------------------------------------------
// Tensor-core helpers (baseline ISA, plain sm_103-compatible PTX)
// ---------------------------------------------------------------------------
__device__ __forceinline__ uint32_t smem_u32(const void* p) {
    uint32_t a;
    asm("{ .reg .u64 t; cvta.to.shared.u64 t, %1; cvt.u32.u64 %0, t; }" : "=r"(a) : "l"(p));
    return a;
}

__device__ __forceinline__ void ldsm4(uint32_t* r, uint32_t addr) {
    asm volatile("ldmatrix.sync.aligned.m8n8.x4.shared.b16 {%0,%1,%2,%3}, [%4];"
                 : "=r"(r[0]), "=r"(r[1]), "=r"(r[2]), "=r"(r[3]) : "r"(addr));
}

__device__ __forceinline__ void mma16816(float* d, const uint32_t* a, const uint32_t* b) {
    asm volatile(
        "mma.sync.aligned.m16n8k16.row.col.f32.bf16.bf16.f32 "
        "{%0,%1,%2,%3}, {%4,%5,%6,%7}, {%8,%9}, {%0,%1,%2,%3};"
        : "+f"(d[0]), "+f"(d[1]), "+f"(d[2]), "+f"(d[3])
        : "r"(a[0]), "r"(a[1]), "r"(a[2]), "r"(a[3]), "r"(b[0]), "r"(b[1]));
}

#define CP16(dst, src) \
    asm volatile("cp.async.cg.shared.global [%0], [%1], 16;" :: "r"(dst), "l"(src))
#define CP_COMMIT() asm volatile("cp.async.commit_group;" ::: "memory")
#define CP_WAIT0() asm volatile("cp.async.wait_group 0;" ::: "memory")
#define CP_WAIT1() asm volatile("cp.async.wait_group 1;" ::: "memory")

// Swizzled byte offset in a [rows][64B] tile: conflict-free ldmatrix phases.
__device__ __forceinline__ uint32_t swz(int row, int chunk) {
    return (uint32_t)(row * 64 + ((chunk ^ ((row >> 1) & 3)) << 4));
}

__device__ __forceinline__ uint32_t pack_bf16x2(float a, float b) {
    __nv_bfloat162 t = __floats2bfloat162_rn(a, b);  // a -> low
    return *(uint32_t*)&t;
}

// ---------------------------------------------------------------------------
// bf16-split tensor-core GEMM (validated R6): C[M,N] = A @ Bt^T
// ---------------------------------------------------------------------------
#define BKC 32
#define TILE_B 8192
#define BUF_B (4 * TILE_B)
#define BFG_SMEM (2 * BUF_B)

__global__ void __launch_bounds__(256, 1)
bfgemm_kernel(const __nv_bfloat16* __restrict__ Ah, const __nv_bfloat16* __restrict__ Al,
              const __nv_bfloat16* __restrict__ Bh, const __nv_bfloat16* __restrict__ Bl,
              float* __restrict__ C, int M, int N, int K) {
    extern __shared__ char smem[];
    const uint32_t smem_base = smem_u32(smem);
    const int t = threadIdx.x;
    const int lane = t & 31;
    const int wid = t >> 5;
    const int wm = wid & 1;
    const int wn = wid >> 1;
    const int bm = blockIdx.y * 128;
    const int bn = blockIdx.x * 128;

    const char* srcs[4] = {
        (const char*)(Ah + (size_t)bm * K),
        (const char*)(Al + (size_t)bm * K),
        (const char*)(Bh + (size_t)bn * K),
        (const char*)(Bl + (size_t)bn * K) };

    float acc[4][4][4];
#pragma unroll
    for (int i = 0; i < 4; i++)
#pragma unroll
        for (int j = 0; j < 4; j++)
#pragma unroll
            for (int u = 0; u < 4; u++) acc[i][j][u] = 0.f;

    const int NC = K / BKC;
    const size_t rowb = (size_t)K * 2;

    {
        uint32_t sbase = smem_base;
#pragma unroll
        for (int tl = 0; tl < 4; tl++) {
            const char* src = srcs[tl];
            uint32_t dstt = sbase + tl * TILE_B;
#pragma unroll
            for (int j = 0; j < 2; j++) {
                int idx = t + j * 256;
                int r = idx >> 2, c = idx & 3;
                CP16(dstt + swz(r, c), src + (size_t)r * rowb + c * 16);
            }
        }
        CP_COMMIT();
    }

    for (int ic = 0; ic < NC; ic++) {
        if (ic + 1 < NC) {
            const int k0b = (ic + 1) * BKC * 2;
            uint32_t sbase = smem_base + ((ic + 1) & 1) * BUF_B;
#pragma unroll
            for (int tl = 0; tl < 4; tl++) {
                const char* src = srcs[tl] + k0b;
                uint32_t dstt = sbase + tl * TILE_B;
#pragma unroll
                for (int j = 0; j < 2; j++) {
                    int idx = t + j * 256;
                    int r = idx >> 2, c = idx & 3;
                    CP16(dstt + swz(r, c), src + (size_t)r * rowb + c * 16);
                }
            }
            CP_COMMIT();
            CP_WAIT1();
        } else {
            CP_WAIT0();
        }
        __syncthreads();

        const uint32_t buf = smem_base + (ic & 1) * BUF_B;
        const uint32_t a_h_base = buf;
        const uint32_t a_l_base = buf + TILE_B;
        const uint32_t b_h_base = buf + 2 * TILE_B;
        const uint32_t b_l_base = buf + 3 * TILE_B;

#pragma unroll
        for (int ks = 0; ks < 2; ks++) {
            uint32_t a_h[4][4], a_l[4][4];
#pragma unroll
            for (int mt = 0; mt < 4; mt++) {
                int row = wm * 64 + mt * 16 + (lane & 15);
                int chunk = ks * 2 + (lane >> 4);
                uint32_t off = swz(row, chunk);
                ldsm4(a_h[mt], a_h_base + off);
                ldsm4(a_l[mt], a_l_base + off);
            }
            uint32_t b_h[4][2], b_l[4][2];
#pragma unroll
            for (int np = 0; np < 2; np++) {
                int row = wn * 32 + np * 16 + ((lane >> 4) << 3) + (lane & 7);
                int chunk = ks * 2 + ((lane >> 3) & 1);
                uint32_t off = swz(row, chunk);
                uint32_t r4[4];
                ldsm4(r4, b_h_base + off);
                b_h[np * 2][0] = r4[0]; b_h[np * 2][1] = r4[1];
                b_h[np * 2 + 1][0] = r4[2]; b_h[np * 2 + 1][1] = r4[3];
                ldsm4(r4, b_l_base + off);
                b_l[np * 2][0] = r4[0]; b_l[np * 2][1] = r4[1];
                b_l[np * 2 + 1][0] = r4[2]; b_l[np * 2 + 1][1] = r4[3];
            }
#pragma unroll
            for (int mt = 0; mt < 4; mt++)
#pragma unroll
                for (int nt = 0; nt < 4; nt++) {
                    mma16816(acc[mt][nt], a_h[mt], b_h[nt]);
                    mma16816(acc[mt][nt], a_h[mt], b_l[nt]);
                    mma16816(acc[mt][nt], a_l[mt], b_h[nt]);
                }
        }
        __syncthreads();
    }

#pragma unroll
    for (int mt = 0; mt < 4; mt++) {
#pragma unroll
        for (int nt = 0; nt < 4; nt++) {
            int r0 = bm + wm * 64 + mt * 16 + (lane >> 2);
            int col = bn + wn * 32 + nt * 8 + ((lane & 3) << 1);
            float* p0 = C + (size_t)r0 * N + col;
            float* p1 = C + (size_t)(r0 + 8) * N + col;
            p0[0] = acc[mt][nt][0]; p0[1] = acc[mt][nt][1];
            p1[0] = acc[mt][nt][2]; p1[1] = acc[mt][nt][3];
        }
    }
}

// ---------------------------------------------------------------------------
// Conversions
// ---------------------------------------------------------------------------
__global__ void conv_split_kernel(const float* __restrict__ A,
                                  __nv_bfloat16* __restrict__ Ahi,
                                  __nv_bfloat16* __restrict__ Alo, int total) {
    int i = blockIdx.x * blockDim.x + threadIdx.x;
    if (i >= total) return;
    float v = A[i];
    __nv_bfloat16 h = __float2bfloat16(v);
    Ahi[i] = h;
    Alo[i] = __float2bfloat16(v - __bfloat162float(h));
}

__global__ void conv_transpose_kernel(const float* __restrict__ W,
                                      __nv_bfloat16* __restrict__ Th,
                                      __nv_bfloat16* __restrict__ Tl, int K, int N) {
    __shared__ float tile[32][33];
    int n0 = blockIdx.x * 32, k0 = blockIdx.y * 32;
    int tx = threadIdx.x & 31, ty = threadIdx.x >> 5;
#pragma unroll
    for (int i = 0; i < 32; i += 8)
        tile[ty + i][tx] = W[(size_t)(k0 + ty + i) * N + n0 + tx];
    __syncthreads();
#pragma unroll
    for (int i = 0; i < 32; i += 8) {
        float v = tile[tx][ty + i];
        __nv_bfloat16 h = __float2bfloat16(v);
        size_t o = (size_t)(n0 + ty + i) * K + k0 + tx;
        Th[o] = h;
        Tl[o] = __float2bfloat16(v - __bfloat162float(h));
    }
}

// V transpose+split: g_v [b*S+s][kvh*128+d] -> Vt[(b*KV+kvh)*128+d][s]
__global__ void vtrans_split_kernel(const float* __restrict__ V,
                                    __nv_bfloat16* __restrict__ Th,
                                    __nv_bfloat16* __restrict__ Tl) {
    __shared__ float tile[32][33];
    int s0 = blockIdx.x * 32, d0 = blockIdx.y * 32;
    int bk = blockIdx.z;               // b*KV + kvh
    int b = bk >> 2, kvh = bk & 3;
    int tx = threadIdx.x & 31, ty = threadIdx.x >> 5;
#pragma unroll
    for (int i = 0; i < 32; i += 8)
        tile[ty + i][tx] = V[(size_t)(b * S_ + s0 + ty + i) * (KV_ * D_) + kvh * 128 + d0 + tx];
    __syncthreads();
#pragma unroll
    for (int i = 0; i < 32; i += 8) {
        float v = tile[tx][ty + i];
        __nv_bfloat16 h = __float2bfloat16(v);
        size_t o = (size_t)(bk * 128 + d0 + ty + i) * S_ + s0 + tx;
        Th[o] = h;
        Tl[o] = __float2bfloat16(v - __bfloat162float(h));
    }
}

// ---------------------------------------------------------------------------
// RoPE tables + fused rope->bf16 split (optionally folding softmax scale)
// ---------------------------------------------------------------------------
__global__ void build_tables_kernel() {
    int idx = blockIdx.x * blockDim.x + threadIdx.x;
    if (idx >= S_ * 64) return;
    int i = idx & 63;
    int s = idx >> 6;
    double inv = pow(10000.0, -(double)i / 64.0);
    double ang = (double)s * inv;
    g_cos[idx] = (float)cos(ang);
    g_sin[idx] = (float)sin(ang);
}

__global__ void rope_split_kernel(const float* __restrict__ p,
                                  __nv_bfloat16* __restrict__ ph,
                                  __nv_bfloat16* __restrict__ pl,
                                  int nheads, int total, float scale) {
    int idx = blockIdx.x * blockDim.x + threadIdx.x;
    if (idx >= total) return;
    int i = idx & 63;
    int h = (idx >> 6) % nheads;
    int tok = idx / (nheads * 64);
    int s = tok & (S_ - 1);

    float c  = g_cos[s * 64 + i];
    float sn = g_sin[s * 64 + i];

    size_t base = (size_t)tok * (nheads * 128) + h * 128;
    float x1 = p[base + i];
    float x2 = p[base + 64 + i];
    float r1 = (x1 * c - x2 * sn) * scale;
    float r2 = (x2 * c + x1 * sn) * scale;
    __nv_bfloat16 h1 = __float2bfloat16(r1);
    __nv_bfloat16 h2 = __float2bfloat16(r2);
    ph[base + i] = h1;
    pl[base + i] = __float2bfloat16(r1 - __bfloat162float(h1));
    ph[base + 64 + i] = h2;
    pl[base + 64 + i] = __float2bfloat16(r2 - __bfloat162float(h2));
}

// ---------------------------------------------------------------------------
// Tensor-core flash attention (causal, bf16-split QK and PV)
// grid: (S/128, H, B), 256 threads (8 warps). Warp w owns q-rows w*16..+15 and
// all 64 keys of each tile -> in-warp softmax.
// ---------------------------------------------------------------------------
#define ATT_SMEM 131072
// smem layout (byte offsets from base):
//   Q tiles:  (prec*4+dc)*8192,  prec in {0=h,1=l}, dc in 0..3, [128 rows][64B]
//   K tiles:  65536 + (prec*4+dc)*4096, [64 rows][64B]
//   Vt tiles: 98304 + (prec*2+kc)*8192, [128 rows][64B]

__global__ void __launch_bounds__(256, 1)
attn2_kernel(const __nv_bfloat16* __restrict__ qbh, const __nv_bfloat16* __restrict__ qbl,
             const __nv_bfloat16* __restrict__ kbh, const __nv_bfloat16* __restrict__ kbl,
             const __nv_bfloat16* __restrict__ vth, const __nv_bfloat16* __restrict__ vtl,
             __nv_bfloat16* __restrict__ oh, __nv_bfloat16* __restrict__ ol) {
    extern __shared__ char smem[];
    const uint32_t sb = smem_u32(smem);
    const int qt = blockIdx.x, h = blockIdx.y, b = blockIdx.z;
    const int kvh = h >> 2;
    const int t = threadIdx.x, lane = t & 31, w = t >> 5;
    const int q0 = qt * 128;

    // ---- Q load (once) ----
    {
        const __nv_bfloat16* srcs[2] = { qbh, qbl };
#pragma unroll
        for (int j = 0; j < 16; j++) {
            int idx = t + j * 256;
            int prec = idx >> 11, rem = idx & 2047;
            int dc = rem >> 9, rem2 = rem & 511;
            int r = rem2 >> 2, c = rem2 & 3;
            const __nv_bfloat16* src =
                srcs[prec] + (size_t)(b * S_ + q0 + r) * (H_ * D_) + h * 128 + dc * 32 + c * 8;
            CP16(sb + (prec * 4 + dc) * 8192 + swz(r, c), src);
        }
        CP_COMMIT();
    }

    float o_acc[16][4];
#pragma unroll
    for (int i = 0; i < 16; i++)
#pragma unroll
        for (int u = 0; u < 4; u++) o_acc[i][u] = 0.f;
    float m0 = -INFINITY, m1 = -INFINITY, l0 = 0.f, l1 = 0.f;

    for (int kt = 0; kt < q0 + 128; kt += 64) {
        // ---- K, V tile loads ----
#pragma unroll
        for (int j = 0; j < 8; j++) {
            int idx = t + j * 256;
            int prec = idx >> 10, rem = idx & 1023;
            int dc = rem >> 8, rem2 = rem & 255;
            int r = rem2 >> 2, c = rem2 & 3;
            const __nv_bfloat16* src =
                (prec ? kbl : kbh) + (size_t)(b * S_ + kt + r) * (KV_ * D_) + kvh * 128 + dc * 32 + c * 8;
            CP16(sb + 65536 + (prec * 4 + dc) * 4096 + swz(r, c), src);
        }
#pragma unroll
        for (int j = 0; j < 8; j++) {
            int idx = t + j * 256;
            int prec = idx >> 10, rem = idx & 1023;
            int kc = rem >> 9, rem2 = rem & 511;
            int r = rem2 >> 2, c = rem2 & 3;
            const __nv_bfloat16* src =
                (prec ? vtl : vth) + (size_t)((b * KV_ + kvh) * 128 + r) * S_ + kt + kc * 32 + c * 8;
            CP16(sb + 98304 + (prec * 2 + kc) * 8192 + swz(r, c), src);
        }
        CP_COMMIT();
        CP_WAIT0();
        __syncthreads();

        // ---- QK^T (3-term split) ----
        float sf[8][4];
#pragma unroll
        for (int nt = 0; nt < 8; nt++)
#pragma unroll
            for (int u = 0; u < 4; u++) sf[nt][u] = 0.f;

#pragma unroll
        for (int j = 0; j < 8; j++) {
            int dc = j >> 1, ks = j & 1;
            uint32_t ah[4], al[4];
            uint32_t aoff = swz(w * 16 + (lane & 15), ks * 2 + (lane >> 4));
            ldsm4(ah, sb + (0 * 4 + dc) * 8192 + aoff);
            ldsm4(al, sb + (1 * 4 + dc) * 8192 + aoff);
            uint32_t bh[8][2], bl[8][2];
#pragma unroll
            for (int np = 0; np < 4; np++) {
                uint32_t boff = swz(np * 16 + ((lane >> 4) << 3) + (lane & 7),
                                    ks * 2 + ((lane >> 3) & 1));
                uint32_t r4[4];
                ldsm4(r4, sb + 65536 + (0 * 4 + dc) * 4096 + boff);
                bh[np * 2][0] = r4[0]; bh[np * 2][1] = r4[1];
                bh[np * 2 + 1][0] = r4[2]; bh[np * 2 + 1][1] = r4[3];
                ldsm4(r4, sb + 65536 + (1 * 4 + dc) * 4096 + boff);
                bl[np * 2][0] = r4[0]; bl[np * 2][1] = r4[1];
                bl[np * 2 + 1][0] = r4[2]; bl[np * 2 + 1][1] = r4[3];
            }
#pragma unroll
            for (int nt = 0; nt < 8; nt++) {
                mma16816(sf[nt], ah, bh[nt]);
                mma16816(sf[nt], ah, bl[nt]);
                mma16816(sf[nt], al, bh[nt]);
            }
        }

        // ---- causal mask (only near-diagonal tiles) ----
        if (kt + 63 > q0 + w * 16) {
            int row0g = q0 + w * 16 + (lane >> 2);
            int colb = kt + ((lane & 3) << 1);
#pragma unroll
            for (int nt = 0; nt < 8; nt++) {
                int c0 = colb + nt * 8;
                if (c0 > row0g)     sf[nt][0] = -INFINITY;
                if (c0 + 1 > row0g) sf[nt][1] = -INFINITY;
                if (c0 > row0g + 8)     sf[nt][2] = -INFINITY;
                if (c0 + 1 > row0g + 8) sf[nt][3] = -INFINITY;
            }
        }

        // ---- online softmax (in-warp: reduce over 4 lanes) ----
        float mx0 = -INFINITY, mx1 = -INFINITY;
#pragma unroll
        for (int nt = 0; nt < 8; nt++) {
            mx0 = fmaxf(mx0, fmaxf(sf[nt][0], sf[nt][1]));
            mx1 = fmaxf(mx1, fmaxf(sf[nt][2], sf[nt][3]));
        }
        mx0 = fmaxf(mx0, __shfl_xor_sync(0xffffffffu, mx0, 1));
        mx0 = fmaxf(mx0, __shfl_xor_sync(0xffffffffu, mx0, 2));
        mx1 = fmaxf(mx1, __shfl_xor_sync(0xffffffffu, mx1, 1));
        mx1 = fmaxf(mx1, __shfl_xor_sync(0xffffffffu, mx1, 2));
        float mn0 = fmaxf(m0, mx0), mn1 = fmaxf(m1, mx1);
        float corr0 = __expf(m0 - mn0), corr1 = __expf(m1 - mn1);
        float sum0 = 0.f, sum1 = 0.f;
#pragma unroll
        for (int nt = 0; nt < 8; nt++) {
            float p0 = __expf(sf[nt][0] - mn0); sf[nt][0] = p0; sum0 += p0;
            float p1 = __expf(sf[nt][1] - mn0); sf[nt][1] = p1; sum0 += p1;
            float p2 = __expf(sf[nt][2] - mn1); sf[nt][2] = p2; sum1 += p2;
            float p3 = __expf(sf[nt][3] - mn1); sf[nt][3] = p3; sum1 += p3;
        }
        sum0 += __shfl_xor_sync(0xffffffffu, sum0, 1);
        sum0 += __shfl_xor_sync(0xffffffffu, sum0, 2);
        sum1 += __shfl_xor_sync(0xffffffffu, sum1, 1);
        sum1 += __shfl_xor_sync(0xffffffffu, sum1, 2);
        l0 = l0 * corr0 + sum0;
        l1 = l1 * corr1 + sum1;
        m0 = mn0; m1 = mn1;
#pragma unroll
        for (int i = 0; i < 16; i++) {
            o_acc[i][0] *= corr0; o_acc[i][1] *= corr0;
            o_acc[i][2] *= corr1; o_acc[i][3] *= corr1;
        }

        // ---- PV (A = P fragments from registers, 3-term split) ----
#pragma unroll
        for (int s4 = 0; s4 < 4; s4++) {
            // P hi/lo fragments from S tiles {2*s4, 2*s4+1}
            uint32_t ah[4], al[4];
#pragma unroll
            for (int half = 0; half < 2; half++) {
                const float* pp = sf[2 * s4 + half];
                float h0f = __bfloat162float(__float2bfloat16(pp[0]));
                float h1f = __bfloat162float(__float2bfloat16(pp[1]));
                float h2f = __bfloat162float(__float2bfloat16(pp[2]));
                float h3f = __bfloat162float(__float2bfloat16(pp[3]));
                ah[half * 2 + 0] = pack_bf16x2(h0f, h1f);
                ah[half * 2 + 1] = pack_bf16x2(h2f, h3f);
                al[half * 2 + 0] = pack_bf16x2(pp[0] - h0f, pp[1] - h1f);
                al[half * 2 + 1] = pack_bf16x2(pp[2] - h2f, pp[3] - h3f);
            }
            int kc = s4 >> 1;
            uint32_t chunk = (uint32_t)((s4 & 1) * 2 + ((lane >> 3) & 1));
#pragma unroll
            for (int np = 0; np < 8; np++) {
                uint32_t boff = swz(np * 16 + ((lane >> 4) << 3) + (lane & 7), chunk);
                uint32_t r4h[4], r4l[4];
                ldsm4(r4h, sb + 98304 + (0 * 2 + kc) * 8192 + boff);
                ldsm4(r4l, sb + 98304 + (1 * 2 + kc) * 8192 + boff);
                mma16816(o_acc[np * 2], ah, r4h);
                mma16816(o_acc[np * 2], ah, r4l);
                mma16816(o_acc[np * 2], al, r4h);
                mma16816(o_acc[np * 2 + 1], ah, r4h + 2);
                mma16816(o_acc[np * 2 + 1], ah, r4l + 2);
                mma16816(o_acc[np * 2 + 1], al, r4h + 2);
            }
        }
        __syncthreads();
    }

    // ---- epilogue: normalize, split to bf16 hi/lo, write ----
    float inv0 = 1.f / l0, inv1 = 1.f / l1;
    int row0g = q0 + w * 16 + (lane >> 2);
    size_t base0 = (size_t)(b * S_ + row0g) * (H_ * D_) + h * 128 + ((lane & 3) << 1);
    size_t base1 = base0 + 8 * (size_t)(H_ * D_);
#pragma unroll
    for (int nt = 0; nt < 16; nt++) {
        float v0 = o_acc[nt][0] * inv0, v1 = o_acc[nt][1] * inv0;
        float v2 = o_acc[nt][2] * inv1, v3 = o_acc[nt][3] * inv1;
        float h0f = __bfloat162float(__float2bfloat16(v0));
        float h1f = __bfloat162float(__float2bfloat16(v1));
        float h2f = __bfloat162float(__float2bfloat16(v2));
        float h3f = __bfloat162float(__float2bfloat16(v3));
        *(uint32_t*)(oh + base0 + nt * 8) = pack_bf16x2(h0f, h1f);
        *(uint32_t*)(ol + base0 + nt * 8) = pack_bf16x2(v0 - h0f, v1 - h1f);
        *(uint32_t*)(oh + base1 + nt * 8) = pack_bf16x2(h2f, h3f);
        *(uint32_t*)(ol + base1 + nt * 8) = pack_bf16x2(v2 - h2f, v3 - h3f);
    }
}

// ---------------------------------------------------------------------------
// Launch
// ---------------------------------------------------------------------------
extern "C" void kernel_launch(void* const* d_in, const int* in_sizes, int n_in,
                              void* d_out, int out_size) {
    const float *x, *Wq, *Wk, *Wv, *Wo;
    if (in_sizes[0] == NTOK * E_) {
        x  = (const float*)d_in[0];
        Wq = (const float*)d_in[1];
        Wk = (const float*)d_in[2];
        Wv = (const float*)d_in[3];
        Wo = (const float*)d_in[4];
    } else {
        Wk = (const float*)d_in[0];
        Wo = (const float*)d_in[1];
        Wq = (const float*)d_in[2];
        Wv = (const float*)d_in[3];
        x  = (const float*)d_in[4];
    }
    float* out = (float*)d_out;

    float *q, *k, *v;
    cudaGetSymbolAddress((void**)&q, g_q);
    cudaGetSymbolAddress((void**)&k, g_k);
    cudaGetSymbolAddress((void**)&v, g_v);
    __nv_bfloat16 *xh, *xl, *oh, *ol, *qbh, *qbl, *kbh, *kbl, *vth, *vtl;
    cudaGetSymbolAddress((void**)&xh, g_xh);
    cudaGetSymbolAddress((void**)&xl, g_xl);
    cudaGetSymbolAddress((void**)&oh, g_oh);
    cudaGetSymbolAddress((void**)&ol, g_ol);
    cudaGetSymbolAddress((void**)&qbh, g_qbh);
    cudaGetSymbolAddress((void**)&qbl, g_qbl);
    cudaGetSymbolAddress((void**)&kbh, g_kbh);
    cudaGetSymbolAddress((void**)&kbl, g_kbl);
    cudaGetSymbolAddress((void**)&vth, g_vth);
    cudaGetSymbolAddress((void**)&vtl, g_vtl);
    __nv_bfloat16 *Wqt_h, *Wqt_l, *Wkt_h, *Wkt_l, *Wvt_h, *Wvt_l, *Wot_h, *Wot_l;
    cudaGetSymbolAddress((void**)&Wqt_h, g_Wqt_h);
    cudaGetSymbolAddress((void**)&Wqt_l, g_Wqt_l);
    cudaGetSymbolAddress((void**)&Wkt_h, g_Wkt_h);
    cudaGetSymbolAddress((void**)&Wkt_l, g_Wkt_l);
    cudaGetSymbolAddress((void**)&Wvt_h, g_Wvt_h);
    cudaGetSymbolAddress((void**)&Wvt_l, g_Wvt_l);
    cudaGetSymbolAddress((void**)&Wot_h, g_Wot_h);
    cudaGetSymbolAddress((void**)&Wot_l, g_Wot_l);

    cudaFuncSetAttribute(bfgemm_kernel, cudaFuncAttributeMaxDynamicSharedMemorySize, BFG_SMEM);
    cudaFuncSetAttribute(attn2_kernel, cudaFuncAttributeMaxDynamicSharedMemorySize, ATT_SMEM);

    // 0) rope tables
    build_tables_kernel<<<(S_ * 64 + 255) / 256, 256>>>();

    // 1) input conversions
    conv_split_kernel<<<(NTOK * E_ + 255) / 256, 256>>>(x, xh, xl, NTOK * E_);
    {
        dim3 gq((H_ * D_) / 32, E_ / 32);
        conv_transpose_kernel<<<gq, 256>>>(Wq, Wqt_h, Wqt_l, E_, H_ * D_);
        dim3 gk((KV_ * D_) / 32, E_ / 32);
        conv_transpose_kernel<<<gk, 256>>>(Wk, Wkt_h, Wkt_l, E_, KV_ * D_);
        conv_transpose_kernel<<<gk, 256>>>(Wv, Wvt_h, Wvt_l, E_, KV_ * D_);
        dim3 go(E_ / 32, E_ / 32);
        conv_transpose_kernel<<<go, 256>>>(Wo, Wot_h, Wot_l, E_, E_);
    }

    // 2) projections
    {
        dim3 gq((H_ * D_) / 128, NTOK / 128);
        bfgemm_kernel<<<gq, 256, BFG_SMEM>>>(xh, xl, Wqt_h, Wqt_l, q, NTOK, H_ * D_, E_);
        dim3 gk((KV_ * D_) / 128, NTOK / 128);
        bfgemm_kernel<<<gk, 256, BFG_SMEM>>>(xh, xl, Wkt_h, Wkt_l, k, NTOK, KV_ * D_, E_);
        bfgemm_kernel<<<gk, 256, BFG_SMEM>>>(xh, xl, Wvt_h, Wvt_l, v, NTOK, KV_ * D_, E_);
    }

    // 3) rope + operand conversion
    {
        const float scale = 0.08838834764831845f;   // 1/sqrt(128), folded into Q
        int totq = NTOK * H_ * 64;
        rope_split_kernel<<<(totq + 255) / 256, 256>>>(q, qbh, qbl, H_, totq, scale);
        int totk = NTOK * KV_ * 64;
        rope_split_kernel<<<(totk + 255) / 256, 256>>>(k, kbh, kbl, KV_, totk, 1.0f);
        dim3 gv(S_ / 32, D_ / 32, B_ * KV_);
        vtrans_split_kernel<<<gv, 256>>>(v, vth, vtl);
    }

    // 4) tensor-core flash attention -> oh/ol (bf16 hi/lo)
    {
        dim3 ga(S_ / 128, H_, B_);
        attn2_kernel<<<ga, 256, ATT_SMEM>>>(qbh, qbl, kbh, kbl, vth, vtl, oh, ol);
    }

    // 5) output projection
    {
        dim3 go(E_ / 128, NTOK / 128);
        bfgemm_kernel<<<go, 256, BFG_SMEM>>>(oh, ol, Wot_h, Wot_l, out, NTOK, E_, E_);
    }
}